// round 14
// baseline (speedup 1.0000x reference)
#include <cuda_runtime.h>
#include <cstdint>
#include <cstddef>

// ---------------------------------------------------------------------------
// Problem constants
// ---------------------------------------------------------------------------
#define H 64
#define NL 3
#define N_ATOM  100000
#define N_BOND  200000
#define N_MOTIF 50000
#define N_CELL  5000
#define NTOT    355000

#define NCNT    665000
#define NSCAN   665001
#define MAXE    3000000
#define WST_LAYER 53248           // (128+192+256+256)*64
#define WB_TOTAL  (NL * WST_LAYER + NL * 4 * H)

#define SCAN_TILE 1024
#define SCAN_NBLK ((NSCAN + SCAN_TILE - 1) / SCAN_TILE)   // 650

#define CSR_CAP 3072              // smem-staged CSR span capacity (ints)

// ---------------------------------------------------------------------------
// Static scratch
// ---------------------------------------------------------------------------
__device__ __align__(16) float g_xbuf0[NTOT * H];
__device__ __align__(16) float g_xbuf1[NTOT * H];
__device__ __align__(16) int   g_cnt[NSCAN];
__device__ __align__(16) int   g_off[NSCAN];
__device__ __align__(16) int   g_cursor[NCNT];
__device__ __align__(16) int   g_bsums[SCAN_NBLK];
__device__ __align__(16) int   g_csr[MAXE];
__device__ __align__(16) float g_Wst[NL * WST_LAYER];
__device__ __align__(16) float g_bsum[NL * 4 * H];

// Constant tables
__device__ __constant__ int c_CO[9]   = {0, 100000, 300000, 350000, 550000,
                                         600000, 650000, 655000, 660000};
__device__ __constant__ int c_SRCT[9] = {0, 0, 0, 1, 1, 2, 0, 1, 2};
__device__ __constant__ int c_RID[4][3] = {{0,0,0},{1,3,0},{2,4,5},{6,7,8}};
__device__ __constant__ int c_NT[4]   = {N_ATOM, N_BOND, N_MOTIF, N_CELL};
__device__ __constant__ int c_NCH[4]  = {2, 3, 4, 4};
__device__ __constant__ int c_WOFF[4] = {0, 8192, 20480, 36864};

// ---------------------------------------------------------------------------
// Packed fp32x2 helpers
// ---------------------------------------------------------------------------
__device__ __forceinline__ void ffma2(unsigned long long& acc,
                                      unsigned long long a,
                                      unsigned long long b) {
    asm("fma.rn.f32x2 %0, %1, %2, %0;" : "+l"(acc) : "l"(a), "l"(b));
}
__device__ __forceinline__ void fadd2(unsigned long long& acc,
                                      unsigned long long v) {
    asm("add.rn.f32x2 %0, %1, %0;" : "+l"(acc) : "l"(v));
}
__device__ __forceinline__ void fmul2(unsigned long long& acc,
                                      unsigned long long v) {
    asm("mul.rn.f32x2 %0, %1, %0;" : "+l"(acc) : "l"(v));
}
__device__ __forceinline__ unsigned long long pack2(float a) {
    unsigned long long d;
    asm("mov.b64 %0, {%1, %1};" : "=l"(d) : "f"(a));
    return d;
}

// ---------------------------------------------------------------------------
// Setup: weight stacking + bias sums + cnt zeroing in ONE kernel
// ---------------------------------------------------------------------------
__global__ void setup_k(const float* __restrict__ Wr, const float* __restrict__ Wl,
                        const float* __restrict__ bl,
                        float* __restrict__ Wst, float* __restrict__ bsum,
                        int* __restrict__ cnt) {
    int i = blockIdx.x * blockDim.x + threadIdx.x;
    const int woff[5]     = {0, 8192, 20480, 36864, 53248};
    const int rcnt[4]     = {1, 2, 3, 3};
    const int rlist[4][3] = {{0,0,0},{1,3,0},{2,4,5},{6,7,8}};
    if (i < NL * WST_LAYER) {
        int l = i / WST_LAYER;
        int rem = i - l * WST_LAYER;
        int t = 0;
        while (rem >= woff[t + 1]) t++;
        int local = rem - woff[t];
        int krow = local >> 6;
        int col  = local & 63;
        float v;
        if (krow < 64) {
            v = 0.0f;
            for (int j = 0; j < rcnt[t]; j++)
                v += Wr[((size_t)(l * 9 + rlist[t][j]) * 64 + krow) * 64 + col];
        } else {
            int s = (krow >> 6) - 1;
            int r = rlist[t][s];
            int kk = krow & 63;
            v = Wl[((size_t)(l * 9 + r) * 64 + kk) * 64 + col];
        }
        Wst[i] = v;
    } else if (i < WB_TOTAL) {
        int j2 = i - NL * WST_LAYER;
        int l = j2 / (4 * H);
        int rem = j2 - l * 4 * H;
        int t = rem >> 6;
        int col = rem & 63;
        float v = 0.0f;
        for (int j = 0; j < rcnt[t]; j++)
            v += bl[(size_t)(l * 9 + rlist[t][j]) * H + col];
        bsum[j2] = v;
    } else if (i < WB_TOTAL + NSCAN) {
        cnt[i - WB_TOTAL] = 0;
    }
}

// ---------------------------------------------------------------------------
// CSR build.  Edge indices are int32, layout [2,E]: src then dst.
// ---------------------------------------------------------------------------
struct EdgeP {
    const int* ei[9];
    int E[9];
};

__global__ void count_all_k(EdgeP p, int* __restrict__ cnt) {
    int gsz = gridDim.x * blockDim.x;
    int t0  = blockIdx.x * blockDim.x + threadIdx.x;
#pragma unroll
    for (int r = 0; r < 9; r++) {
        const int* d = p.ei[r] + p.E[r];
        int* c = cnt + c_CO[r];
        int E = p.E[r];
        for (int e = t0; e < E; e += gsz) atomicAdd(c + __ldg(d + e), 1);
    }
}

__global__ void scan1_k(const int* __restrict__ in, int* __restrict__ bsums) {
    __shared__ int s[256];
    int b = blockIdx.x, tid = threadIdx.x;
    int base = b * SCAN_TILE + tid * 4;
    int t = 0;
#pragma unroll
    for (int j = 0; j < 4; j++) {
        int i = base + j;
        if (i < NSCAN) t += in[i];
    }
    s[tid] = t;
    __syncthreads();
    for (int d = 128; d > 0; d >>= 1) {
        if (tid < d) s[tid] += s[tid + d];
        __syncthreads();
    }
    if (tid == 0) bsums[b] = s[0];
}

// scan3 (absorbs scan2): each block computes its own prefix over bsums,
// then local exclusive scan + base -> off AND cursor.
__global__ void scan3_k(const int* __restrict__ in, const int* __restrict__ bsums,
                        int* __restrict__ off, int* __restrict__ cur) {
    __shared__ int s[256];
    __shared__ int blockbase;
    int b = blockIdx.x, tid = threadIdx.x;

    int bv = 0;
    for (int j = tid; j < b; j += 256) bv += __ldg(bsums + j);
    s[tid] = bv;
    __syncthreads();
    for (int d = 128; d > 0; d >>= 1) {
        if (tid < d) s[tid] += s[tid + d];
        __syncthreads();
    }
    if (tid == 0) blockbase = s[0];
    __syncthreads();

    int base = b * SCAN_TILE + tid * 4;
    int v[4];
    int t = 0;
#pragma unroll
    for (int j = 0; j < 4; j++) {
        int i = base + j;
        v[j] = (i < NSCAN) ? in[i] : 0;
        t += v[j];
    }
    s[tid] = t;
    __syncthreads();
    for (int d = 1; d < 256; d <<= 1) {
        int x = (tid >= d) ? s[tid - d] : 0;
        __syncthreads();
        s[tid] += x;
        __syncthreads();
    }
    int run = blockbase + s[tid] - t;
#pragma unroll
    for (int j = 0; j < 4; j++) {
        int i = base + j;
        if (i < NSCAN) {
            off[i] = run;
            if (i < NCNT) cur[i] = run;
        }
        run += v[j];
    }
}

__global__ void fill_k(EdgeP p, int* __restrict__ cursor, int* __restrict__ csr) {
    int gsz = gridDim.x * blockDim.x;
    int t0  = blockIdx.x * blockDim.x + threadIdx.x;
#pragma unroll
    for (int r = 0; r < 9; r++) {
        const int* s = p.ei[r];
        const int* d = p.ei[r] + p.E[r];
        int* c = cursor + c_CO[r];
        int E = p.E[r];
        for (int e = t0; e < E; e += gsz) {
            int pos = atomicAdd(c + __ldg(d + e), 1);
            csr[pos] = __ldg(s + e);
        }
    }
}

// ---------------------------------------------------------------------------
// Fused layer kernel: 64-row tiles, 2x8 f32x2 micro-tile (halved pack movs),
// smem-staged CSR, dual-row 4-wide gather chains + batched predicated tails.
// Grid block -> (type, tile): atom 1563 | bond 3125 | motif 782 | cell 79.
// ---------------------------------------------------------------------------
#define GRID_GEMM 5549

struct GemmP {
    const float* x[4];
    float* out[4];
    const float* Wst;
    const float* bsum;
    const int* off;
    const int* csr;
};

__global__ void __launch_bounds__(256, 4)
gemm_gather_k(GemmP p) {
    __shared__ __align__(16) float Xs[64 * 64];    // 16KB
    __shared__ __align__(16) float Ws[64 * 64];    // 16KB
    __shared__ __align__(16) int   csr_s[CSR_CAP]; // 12KB
    __shared__ int off_s[65];

    int b = blockIdx.x;
    int t, row0;
    if (b < 1563)      { t = 0; row0 = b * 64; }
    else if (b < 4688) { t = 1; row0 = (b - 1563) * 64; }
    else if (b < 5470) { t = 2; row0 = (b - 4688) * 64; }
    else               { t = 3; row0 = (b - 5470) * 64; }

    const int n       = c_NT[t];
    const int nchunks = c_NCH[t];
    const float* W0   = p.Wst + c_WOFF[t];
    const float* X    = p.x[t];
    const int nrows   = (n - row0 < 64) ? (n - row0) : 64;

    const int tid  = threadIdx.x;
    const int tx   = tid & 7;       // col group: 8 cols (8tx..8tx+7)
    const int ty   = tid >> 3;      // row pair: rows 2ty, 2ty+1  (0..31)
    const int w    = tid >> 5;
    const int lane = tid & 31;

    // 2 rows x 4 col-pairs
    unsigned long long acc[2][4];
#pragma unroll
    for (int r = 0; r < 2; r++)
#pragma unroll
        for (int q = 0; q < 4; q++) acc[r][q] = 0ull;

    for (int c = 0; c < nchunks; c++) {
        // --- load W chunk (4096 floats) ---
#pragma unroll
        for (int i = 0; i < 4; i++) {
            int idx = tid + i * 256;
            ((float4*)Ws)[idx] = ((const float4*)(W0 + c * 4096))[idx];
        }
        // --- fill X chunk ---
        if (c == 0) {
#pragma unroll
            for (int i = 0; i < 4; i++) {
                int idx = tid + i * 256;
                int lr = idx >> 4;
                int c4 = idx & 15;
                int gr = row0 + lr;
                float4 v = make_float4(0.f, 0.f, 0.f, 0.f);
                if (gr < n) v = *(const float4*)(X + (size_t)gr * H + c4 * 4);
                ((float4*)Xs)[idx] = v;
            }
        } else {
            int rel = c_RID[t][c - 1];
            const unsigned long long* __restrict__ xs2 =
                (const unsigned long long*)p.x[c_SRCT[rel]];   // row = 32 u64
            const int* __restrict__ offr = p.off + c_CO[rel];
            const int* __restrict__ csr  = p.csr;

            if (tid <= nrows) off_s[tid] = __ldg(offr + row0 + tid);
            __syncthreads();
            int base0 = off_s[0];
            int span  = off_s[nrows] - base0;
            bool staged = (span <= CSR_CAP);
            if (staged) {
                for (int i = tid; i < span; i += 256)
                    csr_s[i] = __ldg(csr + base0 + i);
            }
            __syncthreads();

            if (staged) {
                const int* ks = csr_s - base0;
#pragma unroll 1
                for (int i = 0; i < 4; i++) {
                    int lrA = w * 8 + i;
                    int lrB = lrA + 4;
                    int sA = 0, eA = 0, sB = 0, eB = 0;
                    if (lrA < nrows) { sA = off_s[lrA]; eA = off_s[lrA + 1]; }
                    if (lrB < nrows) { sB = off_s[lrB]; eB = off_s[lrB + 1]; }
                    unsigned long long aA = 0ull, aB = 0ull;
                    int kA = sA, kB = sB;
                    // dual independent 4-wide chains (MLP 8)
                    while (kA + 3 < eA && kB + 3 < eB) {
                        int a0 = ks[kA], a1 = ks[kA+1], a2 = ks[kA+2], a3 = ks[kA+3];
                        int b0 = ks[kB], b1 = ks[kB+1], b2 = ks[kB+2], b3 = ks[kB+3];
                        unsigned long long vA0 = __ldg(xs2 + (size_t)a0 * 32 + lane);
                        unsigned long long vA1 = __ldg(xs2 + (size_t)a1 * 32 + lane);
                        unsigned long long vA2 = __ldg(xs2 + (size_t)a2 * 32 + lane);
                        unsigned long long vA3 = __ldg(xs2 + (size_t)a3 * 32 + lane);
                        unsigned long long vB0 = __ldg(xs2 + (size_t)b0 * 32 + lane);
                        unsigned long long vB1 = __ldg(xs2 + (size_t)b1 * 32 + lane);
                        unsigned long long vB2 = __ldg(xs2 + (size_t)b2 * 32 + lane);
                        unsigned long long vB3 = __ldg(xs2 + (size_t)b3 * 32 + lane);
                        fadd2(vA0, vA1); fadd2(vA2, vA3); fadd2(vA0, vA2); fadd2(aA, vA0);
                        fadd2(vB0, vB1); fadd2(vB2, vB3); fadd2(vB0, vB2); fadd2(aB, vB0);
                        kA += 4; kB += 4;
                    }
                    while (kA + 3 < eA) {
                        int a0 = ks[kA], a1 = ks[kA+1], a2 = ks[kA+2], a3 = ks[kA+3];
                        unsigned long long v0 = __ldg(xs2 + (size_t)a0 * 32 + lane);
                        unsigned long long v1 = __ldg(xs2 + (size_t)a1 * 32 + lane);
                        unsigned long long v2 = __ldg(xs2 + (size_t)a2 * 32 + lane);
                        unsigned long long v3 = __ldg(xs2 + (size_t)a3 * 32 + lane);
                        fadd2(v0, v1); fadd2(v2, v3); fadd2(v0, v2); fadd2(aA, v0);
                        kA += 4;
                    }
                    while (kB + 3 < eB) {
                        int b0 = ks[kB], b1 = ks[kB+1], b2 = ks[kB+2], b3 = ks[kB+3];
                        unsigned long long v0 = __ldg(xs2 + (size_t)b0 * 32 + lane);
                        unsigned long long v1 = __ldg(xs2 + (size_t)b1 * 32 + lane);
                        unsigned long long v2 = __ldg(xs2 + (size_t)b2 * 32 + lane);
                        unsigned long long v3 = __ldg(xs2 + (size_t)b3 * 32 + lane);
                        fadd2(v0, v1); fadd2(v2, v3); fadd2(v0, v2); fadd2(aB, v0);
                        kB += 4;
                    }
                    // batched predicated tails: all 6 LDGs in one wave
                    {
                        int rA = eA - kA;           // 0..3
                        int rB = eB - kB;           // 0..3
                        unsigned long long t0 = 0ull, t1 = 0ull, t2 = 0ull;
                        unsigned long long u0 = 0ull, u1 = 0ull, u2 = 0ull;
                        if (rA > 0) t0 = __ldg(xs2 + (size_t)ks[kA]     * 32 + lane);
                        if (rA > 1) t1 = __ldg(xs2 + (size_t)ks[kA + 1] * 32 + lane);
                        if (rA > 2) t2 = __ldg(xs2 + (size_t)ks[kA + 2] * 32 + lane);
                        if (rB > 0) u0 = __ldg(xs2 + (size_t)ks[kB]     * 32 + lane);
                        if (rB > 1) u1 = __ldg(xs2 + (size_t)ks[kB + 1] * 32 + lane);
                        if (rB > 2) u2 = __ldg(xs2 + (size_t)ks[kB + 2] * 32 + lane);
                        fadd2(t0, t1); fadd2(t0, t2); fadd2(aA, t0);
                        fadd2(u0, u1); fadd2(u0, u2); fadd2(aB, u0);
                    }
                    int degA = eA - sA, degB = eB - sB;
                    fmul2(aA, pack2(1.0f / (float)(degA > 1 ? degA : 1)));
                    fmul2(aB, pack2(1.0f / (float)(degB > 1 ? degB : 1)));
                    ((unsigned long long*)(Xs + lrA * 64))[lane] = aA;
                    ((unsigned long long*)(Xs + lrB * 64))[lane] = aB;
                }
            } else {
                // rare fallback: direct global CSR reads, per-row sequential
#pragma unroll 1
                for (int i = 0; i < 8; i++) {
                    int lr = w * 8 + i;
                    unsigned long long a = 0ull;
                    if (lr < nrows) {
                        int s = off_s[lr];
                        int e = off_s[lr + 1];
                        for (int k = s; k < e; k++) {
                            int i0 = __ldg(csr + k);
                            unsigned long long v0 = __ldg(xs2 + (size_t)i0 * 32 + lane);
                            fadd2(a, v0);
                        }
                        int deg = e - s;
                        fmul2(a, pack2(1.0f / (float)(deg > 1 ? deg : 1)));
                    }
                    ((unsigned long long*)(Xs + lr * 64))[lane] = a;
                }
            }
        }
        __syncthreads();
        // --- packed FFMA: 2 rows x 8 cols per thread ---
#pragma unroll
        for (int k4 = 0; k4 < 16; k4++) {
            float4 xr0 = ((float4*)Xs)[(ty * 2    ) * 16 + k4];
            float4 xr1 = ((float4*)Xs)[(ty * 2 + 1) * 16 + k4];
#pragma unroll
            for (int kk = 0; kk < 4; kk++) {
                int k = k4 * 4 + kk;
                ulonglong2 w01 = ((ulonglong2*)Ws)[k * 16 + tx * 2];
                ulonglong2 w23 = ((ulonglong2*)Ws)[k * 16 + tx * 2 + 1];
                unsigned long long a0 = pack2((&xr0.x)[kk]);
                unsigned long long a1 = pack2((&xr1.x)[kk]);
                ffma2(acc[0][0], a0, w01.x); ffma2(acc[0][1], a0, w01.y);
                ffma2(acc[0][2], a0, w23.x); ffma2(acc[0][3], a0, w23.y);
                ffma2(acc[1][0], a1, w01.x); ffma2(acc[1][1], a1, w01.y);
                ffma2(acc[1][2], a1, w23.x); ffma2(acc[1][3], a1, w23.y);
            }
        }
        __syncthreads();
    }

    float4 b0 = *(const float4*)(p.bsum + t * 64 + tx * 8);
    float4 b1 = *(const float4*)(p.bsum + t * 64 + tx * 8 + 4);
    float* out = p.out[t];
#pragma unroll
    for (int r = 0; r < 2; r++) {
        int gr = row0 + ty * 2 + r;
        if (gr < n) {
            float2 p0 = *(float2*)&acc[r][0];
            float2 p1 = *(float2*)&acc[r][1];
            float2 p2 = *(float2*)&acc[r][2];
            float2 p3 = *(float2*)&acc[r][3];
            float4 o0, o1;
            o0.x = fmaxf(p0.x + b0.x, 0.f);
            o0.y = fmaxf(p0.y + b0.y, 0.f);
            o0.z = fmaxf(p1.x + b0.z, 0.f);
            o0.w = fmaxf(p1.y + b0.w, 0.f);
            o1.x = fmaxf(p2.x + b1.x, 0.f);
            o1.y = fmaxf(p2.y + b1.y, 0.f);
            o1.z = fmaxf(p3.x + b1.z, 0.f);
            o1.w = fmaxf(p3.y + b1.w, 0.f);
            *(float4*)(out + (size_t)gr * H + tx * 8)     = o0;
            *(float4*)(out + (size_t)gr * H + tx * 8 + 4) = o1;
        }
    }
}

// ---------------------------------------------------------------------------
// Head: out[row] = softplus(cell[row] @ projW + projb) @ outW + outb
// ---------------------------------------------------------------------------
__global__ void head_k(const float* __restrict__ X, const float* __restrict__ W,
                       const float* __restrict__ b, const float* __restrict__ ow,
                       const float* __restrict__ ob, float* __restrict__ out, int n) {
    __shared__ float Ws[H * H];
    for (int i = threadIdx.x; i < H * H; i += blockDim.x) Ws[i] = W[i];
    __syncthreads();

    int warp = threadIdx.x >> 5;
    int lane = threadIdx.x & 31;
    int row  = blockIdx.x * (blockDim.x >> 5) + warp;
    if (row >= n) return;

    const float* x = X + (size_t)row * H;
    float in_lo = x[lane];
    float in_hi = x[lane + 32];
    float a0 = b[lane];
    float a1 = b[lane + 32];

#pragma unroll
    for (int k = 0; k < 32; k++) {
        float a = __shfl_sync(0xffffffffu, in_lo, k);
        a0 += a * Ws[k * H + lane];
        a1 += a * Ws[k * H + lane + 32];
    }
#pragma unroll
    for (int k = 0; k < 32; k++) {
        float a = __shfl_sync(0xffffffffu, in_hi, k);
        a0 += a * Ws[(k + 32) * H + lane];
        a1 += a * Ws[(k + 32) * H + lane + 32];
    }
    a0 = fmaxf(a0, 0.0f) + log1pf(expf(-fabsf(a0)));
    a1 = fmaxf(a1, 0.0f) + log1pf(expf(-fabsf(a1)));
    float s = a0 * ow[lane] + a1 * ow[lane + 32];
#pragma unroll
    for (int o = 16; o > 0; o >>= 1) s += __shfl_down_sync(0xffffffffu, s, o);
    if (lane == 0) out[row] = s + ob[0];
}

// ---------------------------------------------------------------------------
// Host orchestration
// ---------------------------------------------------------------------------
extern "C" void kernel_launch(void* const* d_in, const int* in_sizes, int n_in,
                              void* d_out, int out_size) {
    const float* x_in[4] = {(const float*)d_in[0], (const float*)d_in[1],
                            (const float*)d_in[2], (const float*)d_in[3]};
    const float* Wl    = (const float*)d_in[4];
    const float* bl    = (const float*)d_in[5];
    const float* Wr    = (const float*)d_in[6];
    const float* projW = (const float*)d_in[7];
    const float* projb = (const float*)d_in[8];
    const float* outW  = (const float*)d_in[9];
    const float* outb  = (const float*)d_in[10];

    EdgeP ep;
    for (int r = 0; r < 9; r++) {
        ep.ei[r] = (const int*)d_in[11 + r];
        ep.E[r]  = in_sizes[11 + r] / 2;
    }

    const int ROFF[4] = {0, 100000, 300000, 350000};

    float *buf0, *buf1, *Wst, *bsum;
    int *cnt, *off, *cursor, *bsums, *csr;
    cudaGetSymbolAddress((void**)&buf0,   g_xbuf0);
    cudaGetSymbolAddress((void**)&buf1,   g_xbuf1);
    cudaGetSymbolAddress((void**)&cnt,    g_cnt);
    cudaGetSymbolAddress((void**)&off,    g_off);
    cudaGetSymbolAddress((void**)&cursor, g_cursor);
    cudaGetSymbolAddress((void**)&bsums,  g_bsums);
    cudaGetSymbolAddress((void**)&csr,    g_csr);
    cudaGetSymbolAddress((void**)&Wst,    g_Wst);
    cudaGetSymbolAddress((void**)&bsum,   g_bsum);

    const int TB = 256;

    // 1. setup: weight stacking + bias sums + cnt zeroing (one launch)
    setup_k<<<(WB_TOTAL + NSCAN + TB - 1) / TB, TB>>>(Wr, Wl, bl, Wst, bsum, cnt);

    // 2. CSR build: count, block-sums, scan(+cursor), fill  (4 launches)
    count_all_k<<<2048, TB>>>(ep, cnt);
    scan1_k<<<SCAN_NBLK, 256>>>(cnt, bsums);
    scan3_k<<<SCAN_NBLK, 256>>>(cnt, bsums, off, cursor);
    fill_k<<<2048, TB>>>(ep, cursor, csr);

    // 3. layers (first gemm is launch #6 -> ncu -s 5 -c 1 captures it)
    for (int l = 0; l < NL; l++) {
        GemmP gp;
        float* xnext = (l % 2 == 0) ? buf0 : buf1;
        const float* prev = (l % 2 == 0) ? buf1 : buf0;
        for (int t = 0; t < 4; t++) {
            gp.x[t]   = (l == 0) ? x_in[t] : (prev + (size_t)ROFF[t] * H);
            gp.out[t] = xnext + (size_t)ROFF[t] * H;
        }
        gp.Wst  = Wst + (size_t)l * WST_LAYER;
        gp.bsum = bsum + (size_t)l * 4 * H;
        gp.off  = off;
        gp.csr  = csr;
        gemm_gather_k<<<GRID_GEMM, TB>>>(gp);
    }

    // 4. head
    {
        const float* xcell = buf0 + (size_t)ROFF[3] * H;
        int rows_per_block = TB / 32;
        int g = (N_CELL + rows_per_block - 1) / rows_per_block;
        head_k<<<g, TB>>>(xcell, projW, projb, outW, outb, (float*)d_out, N_CELL);
    }
}

// round 15
// speedup vs baseline: 1.2623x; 1.2623x over previous
#include <cuda_runtime.h>
#include <cstdint>
#include <cstddef>

// ---------------------------------------------------------------------------
// Problem constants
// ---------------------------------------------------------------------------
#define H 64
#define NL 3
#define N_ATOM  100000
#define N_BOND  200000
#define N_MOTIF 50000
#define N_CELL  5000
#define NTOT    355000

#define NCNT    665000
#define NSCAN   665001
#define MAXE    3000000
#define WST_LAYER 53248           // (128+192+256+256)*64
#define WB_TOTAL  (NL * WST_LAYER + NL * 4 * H)

#define SCAN_TILE 1024
#define SCAN_NBLK ((NSCAN + SCAN_TILE - 1) / SCAN_TILE)   // 650

#define CSR_CAP 3072              // smem-staged CSR span capacity (ints)
#define XS_STRIDE 68              // padded row stride (floats) — kills 2-way
                                  // bank conflict on xr LDS.128 (1088B % 128 != 0)

// ---------------------------------------------------------------------------
// Static scratch
// ---------------------------------------------------------------------------
__device__ __align__(16) float g_xbuf0[NTOT * H];
__device__ __align__(16) float g_xbuf1[NTOT * H];
__device__ __align__(16) int   g_cnt[NSCAN];
__device__ __align__(16) int   g_off[NSCAN];
__device__ __align__(16) int   g_cursor[NCNT];
__device__ __align__(16) int   g_bsums[SCAN_NBLK];
__device__ __align__(16) int   g_csr[MAXE];
__device__ __align__(16) float g_Wst[NL * WST_LAYER];
__device__ __align__(16) float g_bsum[NL * 4 * H];

// Constant tables
__device__ __constant__ int c_CO[9]   = {0, 100000, 300000, 350000, 550000,
                                         600000, 650000, 655000, 660000};
__device__ __constant__ int c_SRCT[9] = {0, 0, 0, 1, 1, 2, 0, 1, 2};
__device__ __constant__ int c_RID[4][3] = {{0,0,0},{1,3,0},{2,4,5},{6,7,8}};
__device__ __constant__ int c_NT[4]   = {N_ATOM, N_BOND, N_MOTIF, N_CELL};
__device__ __constant__ int c_NCH[4]  = {2, 3, 4, 4};
__device__ __constant__ int c_WOFF[4] = {0, 8192, 20480, 36864};

// ---------------------------------------------------------------------------
// Packed fp32x2 helpers
// ---------------------------------------------------------------------------
__device__ __forceinline__ void ffma2(unsigned long long& acc,
                                      unsigned long long a,
                                      unsigned long long b) {
    asm("fma.rn.f32x2 %0, %1, %2, %0;" : "+l"(acc) : "l"(a), "l"(b));
}
__device__ __forceinline__ void fadd2(unsigned long long& acc,
                                      unsigned long long v) {
    asm("add.rn.f32x2 %0, %1, %0;" : "+l"(acc) : "l"(v));
}
__device__ __forceinline__ void fmul2(unsigned long long& acc,
                                      unsigned long long v) {
    asm("mul.rn.f32x2 %0, %1, %0;" : "+l"(acc) : "l"(v));
}
__device__ __forceinline__ unsigned long long pack2(float a) {
    unsigned long long d;
    asm("mov.b64 %0, {%1, %1};" : "=l"(d) : "f"(a));
    return d;
}

// ---------------------------------------------------------------------------
// Setup: weight stacking + bias sums + cnt zeroing in ONE kernel
// ---------------------------------------------------------------------------
__global__ void setup_k(const float* __restrict__ Wr, const float* __restrict__ Wl,
                        const float* __restrict__ bl,
                        float* __restrict__ Wst, float* __restrict__ bsum,
                        int* __restrict__ cnt) {
    int i = blockIdx.x * blockDim.x + threadIdx.x;
    const int woff[5]     = {0, 8192, 20480, 36864, 53248};
    const int rcnt[4]     = {1, 2, 3, 3};
    const int rlist[4][3] = {{0,0,0},{1,3,0},{2,4,5},{6,7,8}};
    if (i < NL * WST_LAYER) {
        int l = i / WST_LAYER;
        int rem = i - l * WST_LAYER;
        int t = 0;
        while (rem >= woff[t + 1]) t++;
        int local = rem - woff[t];
        int krow = local >> 6;
        int col  = local & 63;
        float v;
        if (krow < 64) {
            v = 0.0f;
            for (int j = 0; j < rcnt[t]; j++)
                v += Wr[((size_t)(l * 9 + rlist[t][j]) * 64 + krow) * 64 + col];
        } else {
            int s = (krow >> 6) - 1;
            int r = rlist[t][s];
            int kk = krow & 63;
            v = Wl[((size_t)(l * 9 + r) * 64 + kk) * 64 + col];
        }
        Wst[i] = v;
    } else if (i < WB_TOTAL) {
        int j2 = i - NL * WST_LAYER;
        int l = j2 / (4 * H);
        int rem = j2 - l * 4 * H;
        int t = rem >> 6;
        int col = rem & 63;
        float v = 0.0f;
        for (int j = 0; j < rcnt[t]; j++)
            v += bl[(size_t)(l * 9 + rlist[t][j]) * H + col];
        bsum[j2] = v;
    } else if (i < WB_TOTAL + NSCAN) {
        cnt[i - WB_TOTAL] = 0;
    }
}

// ---------------------------------------------------------------------------
// CSR build.  Edge indices are int32, layout [2,E]: src then dst.
// ---------------------------------------------------------------------------
struct EdgeP {
    const int* ei[9];
    int E[9];
};

__global__ void count_all_k(EdgeP p, int* __restrict__ cnt) {
    int gsz = gridDim.x * blockDim.x;
    int t0  = blockIdx.x * blockDim.x + threadIdx.x;
#pragma unroll
    for (int r = 0; r < 9; r++) {
        const int* d = p.ei[r] + p.E[r];
        int* c = cnt + c_CO[r];
        int E = p.E[r];
        for (int e = t0; e < E; e += gsz) atomicAdd(c + __ldg(d + e), 1);
    }
}

__global__ void scan1_k(const int* __restrict__ in, int* __restrict__ bsums) {
    __shared__ int s[256];
    int b = blockIdx.x, tid = threadIdx.x;
    int base = b * SCAN_TILE + tid * 4;
    int t = 0;
#pragma unroll
    for (int j = 0; j < 4; j++) {
        int i = base + j;
        if (i < NSCAN) t += in[i];
    }
    s[tid] = t;
    __syncthreads();
    for (int d = 128; d > 0; d >>= 1) {
        if (tid < d) s[tid] += s[tid + d];
        __syncthreads();
    }
    if (tid == 0) bsums[b] = s[0];
}

// scan3 (absorbs scan2): each block computes its own prefix over bsums,
// then local exclusive scan + base -> off AND cursor.
__global__ void scan3_k(const int* __restrict__ in, const int* __restrict__ bsums,
                        int* __restrict__ off, int* __restrict__ cur) {
    __shared__ int s[256];
    __shared__ int blockbase;
    int b = blockIdx.x, tid = threadIdx.x;

    int bv = 0;
    for (int j = tid; j < b; j += 256) bv += __ldg(bsums + j);
    s[tid] = bv;
    __syncthreads();
    for (int d = 128; d > 0; d >>= 1) {
        if (tid < d) s[tid] += s[tid + d];
        __syncthreads();
    }
    if (tid == 0) blockbase = s[0];
    __syncthreads();

    int base = b * SCAN_TILE + tid * 4;
    int v[4];
    int t = 0;
#pragma unroll
    for (int j = 0; j < 4; j++) {
        int i = base + j;
        v[j] = (i < NSCAN) ? in[i] : 0;
        t += v[j];
    }
    s[tid] = t;
    __syncthreads();
    for (int d = 1; d < 256; d <<= 1) {
        int x = (tid >= d) ? s[tid - d] : 0;
        __syncthreads();
        s[tid] += x;
        __syncthreads();
    }
    int run = blockbase + s[tid] - t;
#pragma unroll
    for (int j = 0; j < 4; j++) {
        int i = base + j;
        if (i < NSCAN) {
            off[i] = run;
            if (i < NCNT) cur[i] = run;
        }
        run += v[j];
    }
}

__global__ void fill_k(EdgeP p, int* __restrict__ cursor, int* __restrict__ csr) {
    int gsz = gridDim.x * blockDim.x;
    int t0  = blockIdx.x * blockDim.x + threadIdx.x;
#pragma unroll
    for (int r = 0; r < 9; r++) {
        const int* s = p.ei[r];
        const int* d = p.ei[r] + p.E[r];
        int* c = cursor + c_CO[r];
        int E = p.E[r];
        for (int e = t0; e < E; e += gsz) {
            int pos = atomicAdd(c + __ldg(d + e), 1);
            csr[pos] = __ldg(s + e);
        }
    }
}

// ---------------------------------------------------------------------------
// Fused layer kernel: 64-row tiles, 4x4 f32x2 micro-tile (R13 core), padded
// Xs stride (bank-conflict-free xr loads), smem-staged CSR, dual-row 4-wide
// gather chains + batched predicated tails.
// Grid block -> (type, tile): atom 1563 | bond 3125 | motif 782 | cell 79.
// ---------------------------------------------------------------------------
#define GRID_GEMM 5549

struct GemmP {
    const float* x[4];
    float* out[4];
    const float* Wst;
    const float* bsum;
    const int* off;
    const int* csr;
};

__global__ void __launch_bounds__(256, 4)
gemm_gather_k(GemmP p) {
    __shared__ __align__(16) float Xs[64 * XS_STRIDE];  // 17.4KB (padded)
    __shared__ __align__(16) float Ws[64 * 64];         // 16KB
    __shared__ __align__(16) int   csr_s[CSR_CAP];      // 12KB
    __shared__ int off_s[65];

    int b = blockIdx.x;
    int t, row0;
    if (b < 1563)      { t = 0; row0 = b * 64; }
    else if (b < 4688) { t = 1; row0 = (b - 1563) * 64; }
    else if (b < 5470) { t = 2; row0 = (b - 4688) * 64; }
    else               { t = 3; row0 = (b - 5470) * 64; }

    const int n       = c_NT[t];
    const int nchunks = c_NCH[t];
    const float* W0   = p.Wst + c_WOFF[t];
    const float* X    = p.x[t];
    const int nrows   = (n - row0 < 64) ? (n - row0) : 64;

    const int tid  = threadIdx.x;
    const int tx   = tid & 15;
    const int ty   = tid >> 4;
    const int w    = tid >> 5;
    const int lane = tid & 31;

    unsigned long long acc01[4], acc23[4];
#pragma unroll
    for (int i = 0; i < 4; i++) { acc01[i] = 0ull; acc23[i] = 0ull; }

    for (int c = 0; c < nchunks; c++) {
        // --- load W chunk (4096 floats) ---
#pragma unroll
        for (int i = 0; i < 4; i++) {
            int idx = tid + i * 256;
            ((float4*)Ws)[idx] = ((const float4*)(W0 + c * 4096))[idx];
        }
        // --- fill X chunk ---
        if (c == 0) {
#pragma unroll
            for (int i = 0; i < 4; i++) {
                int idx = tid + i * 256;
                int lr = idx >> 4;
                int c4 = idx & 15;
                int gr = row0 + lr;
                float4 v = make_float4(0.f, 0.f, 0.f, 0.f);
                if (gr < n) v = *(const float4*)(X + (size_t)gr * H + c4 * 4);
                *(float4*)(Xs + lr * XS_STRIDE + c4 * 4) = v;
            }
        } else {
            int rel = c_RID[t][c - 1];
            const unsigned long long* __restrict__ xs2 =
                (const unsigned long long*)p.x[c_SRCT[rel]];   // row = 32 u64
            const int* __restrict__ offr = p.off + c_CO[rel];
            const int* __restrict__ csr  = p.csr;

            if (tid <= nrows) off_s[tid] = __ldg(offr + row0 + tid);
            __syncthreads();
            int base0 = off_s[0];
            int span  = off_s[nrows] - base0;
            bool staged = (span <= CSR_CAP);
            if (staged) {
                for (int i = tid; i < span; i += 256)
                    csr_s[i] = __ldg(csr + base0 + i);
            }
            __syncthreads();

            if (staged) {
                const int* ks = csr_s - base0;
#pragma unroll 1
                for (int i = 0; i < 4; i++) {
                    int lrA = w * 8 + i;
                    int lrB = lrA + 4;
                    int sA = 0, eA = 0, sB = 0, eB = 0;
                    if (lrA < nrows) { sA = off_s[lrA]; eA = off_s[lrA + 1]; }
                    if (lrB < nrows) { sB = off_s[lrB]; eB = off_s[lrB + 1]; }
                    unsigned long long aA = 0ull, aB = 0ull;
                    int kA = sA, kB = sB;
                    // dual independent 4-wide chains (MLP 8)
                    while (kA + 3 < eA && kB + 3 < eB) {
                        int a0 = ks[kA], a1 = ks[kA+1], a2 = ks[kA+2], a3 = ks[kA+3];
                        int b0 = ks[kB], b1 = ks[kB+1], b2 = ks[kB+2], b3 = ks[kB+3];
                        unsigned long long vA0 = __ldg(xs2 + (size_t)a0 * 32 + lane);
                        unsigned long long vA1 = __ldg(xs2 + (size_t)a1 * 32 + lane);
                        unsigned long long vA2 = __ldg(xs2 + (size_t)a2 * 32 + lane);
                        unsigned long long vA3 = __ldg(xs2 + (size_t)a3 * 32 + lane);
                        unsigned long long vB0 = __ldg(xs2 + (size_t)b0 * 32 + lane);
                        unsigned long long vB1 = __ldg(xs2 + (size_t)b1 * 32 + lane);
                        unsigned long long vB2 = __ldg(xs2 + (size_t)b2 * 32 + lane);
                        unsigned long long vB3 = __ldg(xs2 + (size_t)b3 * 32 + lane);
                        fadd2(vA0, vA1); fadd2(vA2, vA3); fadd2(vA0, vA2); fadd2(aA, vA0);
                        fadd2(vB0, vB1); fadd2(vB2, vB3); fadd2(vB0, vB2); fadd2(aB, vB0);
                        kA += 4; kB += 4;
                    }
                    while (kA + 3 < eA) {
                        int a0 = ks[kA], a1 = ks[kA+1], a2 = ks[kA+2], a3 = ks[kA+3];
                        unsigned long long v0 = __ldg(xs2 + (size_t)a0 * 32 + lane);
                        unsigned long long v1 = __ldg(xs2 + (size_t)a1 * 32 + lane);
                        unsigned long long v2 = __ldg(xs2 + (size_t)a2 * 32 + lane);
                        unsigned long long v3 = __ldg(xs2 + (size_t)a3 * 32 + lane);
                        fadd2(v0, v1); fadd2(v2, v3); fadd2(v0, v2); fadd2(aA, v0);
                        kA += 4;
                    }
                    while (kB + 3 < eB) {
                        int b0 = ks[kB], b1 = ks[kB+1], b2 = ks[kB+2], b3 = ks[kB+3];
                        unsigned long long v0 = __ldg(xs2 + (size_t)b0 * 32 + lane);
                        unsigned long long v1 = __ldg(xs2 + (size_t)b1 * 32 + lane);
                        unsigned long long v2 = __ldg(xs2 + (size_t)b2 * 32 + lane);
                        unsigned long long v3 = __ldg(xs2 + (size_t)b3 * 32 + lane);
                        fadd2(v0, v1); fadd2(v2, v3); fadd2(v0, v2); fadd2(aB, v0);
                        kB += 4;
                    }
                    // batched predicated tails: all 6 LDGs in one wave
                    {
                        int rA = eA - kA;           // 0..3
                        int rB = eB - kB;           // 0..3
                        unsigned long long t0 = 0ull, t1 = 0ull, t2 = 0ull;
                        unsigned long long u0 = 0ull, u1 = 0ull, u2 = 0ull;
                        if (rA > 0) t0 = __ldg(xs2 + (size_t)ks[kA]     * 32 + lane);
                        if (rA > 1) t1 = __ldg(xs2 + (size_t)ks[kA + 1] * 32 + lane);
                        if (rA > 2) t2 = __ldg(xs2 + (size_t)ks[kA + 2] * 32 + lane);
                        if (rB > 0) u0 = __ldg(xs2 + (size_t)ks[kB]     * 32 + lane);
                        if (rB > 1) u1 = __ldg(xs2 + (size_t)ks[kB + 1] * 32 + lane);
                        if (rB > 2) u2 = __ldg(xs2 + (size_t)ks[kB + 2] * 32 + lane);
                        fadd2(t0, t1); fadd2(t0, t2); fadd2(aA, t0);
                        fadd2(u0, u1); fadd2(u0, u2); fadd2(aB, u0);
                    }
                    int degA = eA - sA, degB = eB - sB;
                    fmul2(aA, pack2(1.0f / (float)(degA > 1 ? degA : 1)));
                    fmul2(aB, pack2(1.0f / (float)(degB > 1 ? degB : 1)));
                    ((unsigned long long*)(Xs + lrA * XS_STRIDE))[lane] = aA;
                    ((unsigned long long*)(Xs + lrB * XS_STRIDE))[lane] = aB;
                }
            } else {
                // rare fallback: direct global CSR reads, per-row sequential
#pragma unroll 1
                for (int i = 0; i < 8; i++) {
                    int lr = w * 8 + i;
                    unsigned long long a = 0ull;
                    if (lr < nrows) {
                        int s = off_s[lr];
                        int e = off_s[lr + 1];
                        for (int k = s; k < e; k++) {
                            int i0 = __ldg(csr + k);
                            unsigned long long v0 = __ldg(xs2 + (size_t)i0 * 32 + lane);
                            fadd2(a, v0);
                        }
                        int deg = e - s;
                        fmul2(a, pack2(1.0f / (float)(deg > 1 ? deg : 1)));
                    }
                    ((unsigned long long*)(Xs + lr * XS_STRIDE))[lane] = a;
                }
            }
        }
        __syncthreads();
        // --- packed FFMA: 4 rows x 4 cols per thread ---
#pragma unroll
        for (int k4 = 0; k4 < 16; k4++) {
            float4 xr[4];
#pragma unroll
            for (int i = 0; i < 4; i++)
                xr[i] = *(const float4*)(Xs + (ty * 4 + i) * XS_STRIDE + k4 * 4);
#pragma unroll
            for (int j = 0; j < 4; j++) {
                ulonglong2 wv = ((ulonglong2*)Ws)[(k4 * 4 + j) * 16 + tx];
#pragma unroll
                for (int i = 0; i < 4; i++) {
                    unsigned long long aa = pack2((&xr[i].x)[j]);
                    ffma2(acc01[i], aa, wv.x);
                    ffma2(acc23[i], aa, wv.y);
                }
            }
        }
        __syncthreads();
    }

    float4 bb = *(const float4*)(p.bsum + t * 64 + tx * 4);
    float* out = p.out[t];
#pragma unroll
    for (int i = 0; i < 4; i++) {
        int gr = row0 + ty * 4 + i;
        if (gr < n) {
            float2 lo = *(float2*)&acc01[i];
            float2 hi = *(float2*)&acc23[i];
            float4 o;
            o.x = fmaxf(lo.x + bb.x, 0.f);
            o.y = fmaxf(lo.y + bb.y, 0.f);
            o.z = fmaxf(hi.x + bb.z, 0.f);
            o.w = fmaxf(hi.y + bb.w, 0.f);
            *(float4*)(out + (size_t)gr * H + tx * 4) = o;
        }
    }
}

// ---------------------------------------------------------------------------
// Head: out[row] = softplus(cell[row] @ projW + projb) @ outW + outb
// ---------------------------------------------------------------------------
__global__ void head_k(const float* __restrict__ X, const float* __restrict__ W,
                       const float* __restrict__ b, const float* __restrict__ ow,
                       const float* __restrict__ ob, float* __restrict__ out, int n) {
    __shared__ float Ws[H * H];
    for (int i = threadIdx.x; i < H * H; i += blockDim.x) Ws[i] = W[i];
    __syncthreads();

    int warp = threadIdx.x >> 5;
    int lane = threadIdx.x & 31;
    int row  = blockIdx.x * (blockDim.x >> 5) + warp;
    if (row >= n) return;

    const float* x = X + (size_t)row * H;
    float in_lo = x[lane];
    float in_hi = x[lane + 32];
    float a0 = b[lane];
    float a1 = b[lane + 32];

#pragma unroll
    for (int k = 0; k < 32; k++) {
        float a = __shfl_sync(0xffffffffu, in_lo, k);
        a0 += a * Ws[k * H + lane];
        a1 += a * Ws[k * H + lane + 32];
    }
#pragma unroll
    for (int k = 0; k < 32; k++) {
        float a = __shfl_sync(0xffffffffu, in_hi, k);
        a0 += a * Ws[(k + 32) * H + lane];
        a1 += a * Ws[(k + 32) * H + lane + 32];
    }
    a0 = fmaxf(a0, 0.0f) + log1pf(expf(-fabsf(a0)));
    a1 = fmaxf(a1, 0.0f) + log1pf(expf(-fabsf(a1)));
    float s = a0 * ow[lane] + a1 * ow[lane + 32];
#pragma unroll
    for (int o = 16; o > 0; o >>= 1) s += __shfl_down_sync(0xffffffffu, s, o);
    if (lane == 0) out[row] = s + ob[0];
}

// ---------------------------------------------------------------------------
// Host orchestration
// ---------------------------------------------------------------------------
extern "C" void kernel_launch(void* const* d_in, const int* in_sizes, int n_in,
                              void* d_out, int out_size) {
    const float* x_in[4] = {(const float*)d_in[0], (const float*)d_in[1],
                            (const float*)d_in[2], (const float*)d_in[3]};
    const float* Wl    = (const float*)d_in[4];
    const float* bl    = (const float*)d_in[5];
    const float* Wr    = (const float*)d_in[6];
    const float* projW = (const float*)d_in[7];
    const float* projb = (const float*)d_in[8];
    const float* outW  = (const float*)d_in[9];
    const float* outb  = (const float*)d_in[10];

    EdgeP ep;
    for (int r = 0; r < 9; r++) {
        ep.ei[r] = (const int*)d_in[11 + r];
        ep.E[r]  = in_sizes[11 + r] / 2;
    }

    const int ROFF[4] = {0, 100000, 300000, 350000};

    float *buf0, *buf1, *Wst, *bsum;
    int *cnt, *off, *cursor, *bsums, *csr;
    cudaGetSymbolAddress((void**)&buf0,   g_xbuf0);
    cudaGetSymbolAddress((void**)&buf1,   g_xbuf1);
    cudaGetSymbolAddress((void**)&cnt,    g_cnt);
    cudaGetSymbolAddress((void**)&off,    g_off);
    cudaGetSymbolAddress((void**)&cursor, g_cursor);
    cudaGetSymbolAddress((void**)&bsums,  g_bsums);
    cudaGetSymbolAddress((void**)&csr,    g_csr);
    cudaGetSymbolAddress((void**)&Wst,    g_Wst);
    cudaGetSymbolAddress((void**)&bsum,   g_bsum);

    const int TB = 256;

    // 1. setup: weight stacking + bias sums + cnt zeroing (one launch)
    setup_k<<<(WB_TOTAL + NSCAN + TB - 1) / TB, TB>>>(Wr, Wl, bl, Wst, bsum, cnt);

    // 2. CSR build: count, block-sums, scan(+cursor), fill  (4 launches)
    count_all_k<<<2048, TB>>>(ep, cnt);
    scan1_k<<<SCAN_NBLK, 256>>>(cnt, bsums);
    scan3_k<<<SCAN_NBLK, 256>>>(cnt, bsums, off, cursor);
    fill_k<<<2048, TB>>>(ep, cursor, csr);

    // 3. layers (first gemm is launch #6 -> ncu -s 5 -c 1 captures it)
    for (int l = 0; l < NL; l++) {
        GemmP gp;
        float* xnext = (l % 2 == 0) ? buf0 : buf1;
        const float* prev = (l % 2 == 0) ? buf1 : buf0;
        for (int t = 0; t < 4; t++) {
            gp.x[t]   = (l == 0) ? x_in[t] : (prev + (size_t)ROFF[t] * H);
            gp.out[t] = xnext + (size_t)ROFF[t] * H;
        }
        gp.Wst  = Wst + (size_t)l * WST_LAYER;
        gp.bsum = bsum + (size_t)l * 4 * H;
        gp.off  = off;
        gp.csr  = csr;
        gemm_gather_k<<<GRID_GEMM, TB>>>(gp);
    }

    // 4. head
    {
        const float* xcell = buf0 + (size_t)ROFF[3] * H;
        int rows_per_block = TB / 32;
        int g = (N_CELL + rows_per_block - 1) / rows_per_block;
        head_k<<<g, TB>>>(xcell, projW, projb, outW, outb, (float*)d_out, N_CELL);
    }
}

// round 16
// speedup vs baseline: 1.8143x; 1.4373x over previous
#include <cuda_runtime.h>
#include <cstdint>
#include <cstddef>

// ---------------------------------------------------------------------------
// Problem constants
// ---------------------------------------------------------------------------
#define H 64
#define NL 3
#define N_ATOM  100000
#define N_BOND  200000
#define N_MOTIF 50000
#define N_CELL  5000
#define NTOT    355000

#define NCNT    665000
#define NSCAN   665001
#define MAXE    3000000
#define WST_LAYER 53248           // (128+192+256+256)*64
#define WB_TOTAL  (NL * WST_LAYER + NL * 4 * H)

#define SCAN_TILE 1024
#define SCAN_NBLK ((NSCAN + SCAN_TILE - 1) / SCAN_TILE)   // 650

#define CSR_CAP 2560              // smem-staged CSR span (10KB) — shrunk to pay
                                  // for Xs padding while keeping occ=4
#define XS_STRIDE 68              // padded row stride: xr LDS conflict-free

// Block smem: 17408 (Xs) + 16384 (Ws) + 10240 (csr_s) + 260 (off_s)
//           = 44292 B  ->  4 blocks/SM fits under the per-SM smem limit.

// ---------------------------------------------------------------------------
// Static scratch
// ---------------------------------------------------------------------------
__device__ __align__(16) float g_xbuf0[NTOT * H];
__device__ __align__(16) float g_xbuf1[NTOT * H];
__device__ __align__(16) int   g_cnt[NSCAN];
__device__ __align__(16) int   g_off[NSCAN];
__device__ __align__(16) int   g_cursor[NCNT];
__device__ __align__(16) int   g_bsums[SCAN_NBLK];
__device__ __align__(16) int   g_csr[MAXE];
__device__ __align__(16) float g_Wst[NL * WST_LAYER];
__device__ __align__(16) float g_bsum[NL * 4 * H];

// Constant tables
__device__ __constant__ int c_CO[9]   = {0, 100000, 300000, 350000, 550000,
                                         600000, 650000, 655000, 660000};
__device__ __constant__ int c_SRCT[9] = {0, 0, 0, 1, 1, 2, 0, 1, 2};
__device__ __constant__ int c_RID[4][3] = {{0,0,0},{1,3,0},{2,4,5},{6,7,8}};
__device__ __constant__ int c_NT[4]   = {N_ATOM, N_BOND, N_MOTIF, N_CELL};
__device__ __constant__ int c_NCH[4]  = {2, 3, 4, 4};
__device__ __constant__ int c_WOFF[4] = {0, 8192, 20480, 36864};

// ---------------------------------------------------------------------------
// Packed fp32x2 helpers
// ---------------------------------------------------------------------------
__device__ __forceinline__ void ffma2(unsigned long long& acc,
                                      unsigned long long a,
                                      unsigned long long b) {
    asm("fma.rn.f32x2 %0, %1, %2, %0;" : "+l"(acc) : "l"(a), "l"(b));
}
__device__ __forceinline__ void fadd2(unsigned long long& acc,
                                      unsigned long long v) {
    asm("add.rn.f32x2 %0, %1, %0;" : "+l"(acc) : "l"(v));
}
__device__ __forceinline__ void fmul2(unsigned long long& acc,
                                      unsigned long long v) {
    asm("mul.rn.f32x2 %0, %1, %0;" : "+l"(acc) : "l"(v));
}
__device__ __forceinline__ unsigned long long pack2(float a) {
    unsigned long long d;
    asm("mov.b64 %0, {%1, %1};" : "=l"(d) : "f"(a));
    return d;
}

// ---------------------------------------------------------------------------
// Setup: weight stacking + bias sums + cnt zeroing in ONE kernel
// ---------------------------------------------------------------------------
__global__ void setup_k(const float* __restrict__ Wr, const float* __restrict__ Wl,
                        const float* __restrict__ bl,
                        float* __restrict__ Wst, float* __restrict__ bsum,
                        int* __restrict__ cnt) {
    int i = blockIdx.x * blockDim.x + threadIdx.x;
    const int woff[5]     = {0, 8192, 20480, 36864, 53248};
    const int rcnt[4]     = {1, 2, 3, 3};
    const int rlist[4][3] = {{0,0,0},{1,3,0},{2,4,5},{6,7,8}};
    if (i < NL * WST_LAYER) {
        int l = i / WST_LAYER;
        int rem = i - l * WST_LAYER;
        int t = 0;
        while (rem >= woff[t + 1]) t++;
        int local = rem - woff[t];
        int krow = local >> 6;
        int col  = local & 63;
        float v;
        if (krow < 64) {
            v = 0.0f;
            for (int j = 0; j < rcnt[t]; j++)
                v += Wr[((size_t)(l * 9 + rlist[t][j]) * 64 + krow) * 64 + col];
        } else {
            int s = (krow >> 6) - 1;
            int r = rlist[t][s];
            int kk = krow & 63;
            v = Wl[((size_t)(l * 9 + r) * 64 + kk) * 64 + col];
        }
        Wst[i] = v;
    } else if (i < WB_TOTAL) {
        int j2 = i - NL * WST_LAYER;
        int l = j2 / (4 * H);
        int rem = j2 - l * 4 * H;
        int t = rem >> 6;
        int col = rem & 63;
        float v = 0.0f;
        for (int j = 0; j < rcnt[t]; j++)
            v += bl[(size_t)(l * 9 + rlist[t][j]) * H + col];
        bsum[j2] = v;
    } else if (i < WB_TOTAL + NSCAN) {
        cnt[i - WB_TOTAL] = 0;
    }
}

// ---------------------------------------------------------------------------
// CSR build.  Edge indices are int32, layout [2,E]: src then dst.
// ---------------------------------------------------------------------------
struct EdgeP {
    const int* ei[9];
    int E[9];
};

__global__ void count_all_k(EdgeP p, int* __restrict__ cnt) {
    int gsz = gridDim.x * blockDim.x;
    int t0  = blockIdx.x * blockDim.x + threadIdx.x;
#pragma unroll
    for (int r = 0; r < 9; r++) {
        const int* d = p.ei[r] + p.E[r];
        int* c = cnt + c_CO[r];
        int E = p.E[r];
        for (int e = t0; e < E; e += gsz) atomicAdd(c + __ldg(d + e), 1);
    }
}

__global__ void scan1_k(const int* __restrict__ in, int* __restrict__ bsums) {
    __shared__ int s[256];
    int b = blockIdx.x, tid = threadIdx.x;
    int base = b * SCAN_TILE + tid * 4;
    int t = 0;
#pragma unroll
    for (int j = 0; j < 4; j++) {
        int i = base + j;
        if (i < NSCAN) t += in[i];
    }
    s[tid] = t;
    __syncthreads();
    for (int d = 128; d > 0; d >>= 1) {
        if (tid < d) s[tid] += s[tid + d];
        __syncthreads();
    }
    if (tid == 0) bsums[b] = s[0];
}

// scan3 (absorbs scan2): each block computes its own prefix over bsums,
// then local exclusive scan + base -> off AND cursor.
__global__ void scan3_k(const int* __restrict__ in, const int* __restrict__ bsums,
                        int* __restrict__ off, int* __restrict__ cur) {
    __shared__ int s[256];
    __shared__ int blockbase;
    int b = blockIdx.x, tid = threadIdx.x;

    int bv = 0;
    for (int j = tid; j < b; j += 256) bv += __ldg(bsums + j);
    s[tid] = bv;
    __syncthreads();
    for (int d = 128; d > 0; d >>= 1) {
        if (tid < d) s[tid] += s[tid + d];
        __syncthreads();
    }
    if (tid == 0) blockbase = s[0];
    __syncthreads();

    int base = b * SCAN_TILE + tid * 4;
    int v[4];
    int t = 0;
#pragma unroll
    for (int j = 0; j < 4; j++) {
        int i = base + j;
        v[j] = (i < NSCAN) ? in[i] : 0;
        t += v[j];
    }
    s[tid] = t;
    __syncthreads();
    for (int d = 1; d < 256; d <<= 1) {
        int x = (tid >= d) ? s[tid - d] : 0;
        __syncthreads();
        s[tid] += x;
        __syncthreads();
    }
    int run = blockbase + s[tid] - t;
#pragma unroll
    for (int j = 0; j < 4; j++) {
        int i = base + j;
        if (i < NSCAN) {
            off[i] = run;
            if (i < NCNT) cur[i] = run;
        }
        run += v[j];
    }
}

__global__ void fill_k(EdgeP p, int* __restrict__ cursor, int* __restrict__ csr) {
    int gsz = gridDim.x * blockDim.x;
    int t0  = blockIdx.x * blockDim.x + threadIdx.x;
#pragma unroll
    for (int r = 0; r < 9; r++) {
        const int* s = p.ei[r];
        const int* d = p.ei[r] + p.E[r];
        int* c = cursor + c_CO[r];
        int E = p.E[r];
        for (int e = t0; e < E; e += gsz) {
            int pos = atomicAdd(c + __ldg(d + e), 1);
            csr[pos] = __ldg(s + e);
        }
    }
}

// ---------------------------------------------------------------------------
// Fused layer kernel: 64-row tiles, 4x4 f32x2 micro-tile, padded Xs stride
// (conflict-free xr loads, paid for by smaller csr_s to keep occ=4),
// smem-staged CSR, dual-row 4-wide gather chains + batched predicated tails.
// Grid block -> (type, tile): atom 1563 | bond 3125 | motif 782 | cell 79.
// ---------------------------------------------------------------------------
#define GRID_GEMM 5549

struct GemmP {
    const float* x[4];
    float* out[4];
    const float* Wst;
    const float* bsum;
    const int* off;
    const int* csr;
};

__global__ void __launch_bounds__(256, 4)
gemm_gather_k(GemmP p) {
    __shared__ __align__(16) float Xs[64 * XS_STRIDE];  // 17408 B
    __shared__ __align__(16) float Ws[64 * 64];         // 16384 B
    __shared__ __align__(16) int   csr_s[CSR_CAP];      // 10240 B
    __shared__ int off_s[65];                           //   260 B

    int b = blockIdx.x;
    int t, row0;
    if (b < 1563)      { t = 0; row0 = b * 64; }
    else if (b < 4688) { t = 1; row0 = (b - 1563) * 64; }
    else if (b < 5470) { t = 2; row0 = (b - 4688) * 64; }
    else               { t = 3; row0 = (b - 5470) * 64; }

    const int n       = c_NT[t];
    const int nchunks = c_NCH[t];
    const float* W0   = p.Wst + c_WOFF[t];
    const float* X    = p.x[t];
    const int nrows   = (n - row0 < 64) ? (n - row0) : 64;

    const int tid  = threadIdx.x;
    const int tx   = tid & 15;
    const int ty   = tid >> 4;
    const int w    = tid >> 5;
    const int lane = tid & 31;

    unsigned long long acc01[4], acc23[4];
#pragma unroll
    for (int i = 0; i < 4; i++) { acc01[i] = 0ull; acc23[i] = 0ull; }

    for (int c = 0; c < nchunks; c++) {
        // --- load W chunk (4096 floats) ---
#pragma unroll
        for (int i = 0; i < 4; i++) {
            int idx = tid + i * 256;
            ((float4*)Ws)[idx] = ((const float4*)(W0 + c * 4096))[idx];
        }
        // --- fill X chunk ---
        if (c == 0) {
#pragma unroll
            for (int i = 0; i < 4; i++) {
                int idx = tid + i * 256;
                int lr = idx >> 4;
                int c4 = idx & 15;
                int gr = row0 + lr;
                float4 v = make_float4(0.f, 0.f, 0.f, 0.f);
                if (gr < n) v = *(const float4*)(X + (size_t)gr * H + c4 * 4);
                *(float4*)(Xs + lr * XS_STRIDE + c4 * 4) = v;
            }
        } else {
            int rel = c_RID[t][c - 1];
            const unsigned long long* __restrict__ xs2 =
                (const unsigned long long*)p.x[c_SRCT[rel]];   // row = 32 u64
            const int* __restrict__ offr = p.off + c_CO[rel];
            const int* __restrict__ csr  = p.csr;

            if (tid <= nrows) off_s[tid] = __ldg(offr + row0 + tid);
            __syncthreads();
            int base0 = off_s[0];
            int span  = off_s[nrows] - base0;
            bool staged = (span <= CSR_CAP);
            if (staged) {
                for (int i = tid; i < span; i += 256)
                    csr_s[i] = __ldg(csr + base0 + i);
            }
            __syncthreads();

            if (staged) {
                const int* ks = csr_s - base0;
#pragma unroll 1
                for (int i = 0; i < 4; i++) {
                    int lrA = w * 8 + i;
                    int lrB = lrA + 4;
                    int sA = 0, eA = 0, sB = 0, eB = 0;
                    if (lrA < nrows) { sA = off_s[lrA]; eA = off_s[lrA + 1]; }
                    if (lrB < nrows) { sB = off_s[lrB]; eB = off_s[lrB + 1]; }
                    unsigned long long aA = 0ull, aB = 0ull;
                    int kA = sA, kB = sB;
                    // dual independent 4-wide chains (MLP 8)
                    while (kA + 3 < eA && kB + 3 < eB) {
                        int a0 = ks[kA], a1 = ks[kA+1], a2 = ks[kA+2], a3 = ks[kA+3];
                        int b0 = ks[kB], b1 = ks[kB+1], b2 = ks[kB+2], b3 = ks[kB+3];
                        unsigned long long vA0 = __ldg(xs2 + (size_t)a0 * 32 + lane);
                        unsigned long long vA1 = __ldg(xs2 + (size_t)a1 * 32 + lane);
                        unsigned long long vA2 = __ldg(xs2 + (size_t)a2 * 32 + lane);
                        unsigned long long vA3 = __ldg(xs2 + (size_t)a3 * 32 + lane);
                        unsigned long long vB0 = __ldg(xs2 + (size_t)b0 * 32 + lane);
                        unsigned long long vB1 = __ldg(xs2 + (size_t)b1 * 32 + lane);
                        unsigned long long vB2 = __ldg(xs2 + (size_t)b2 * 32 + lane);
                        unsigned long long vB3 = __ldg(xs2 + (size_t)b3 * 32 + lane);
                        fadd2(vA0, vA1); fadd2(vA2, vA3); fadd2(vA0, vA2); fadd2(aA, vA0);
                        fadd2(vB0, vB1); fadd2(vB2, vB3); fadd2(vB0, vB2); fadd2(aB, vB0);
                        kA += 4; kB += 4;
                    }
                    while (kA + 3 < eA) {
                        int a0 = ks[kA], a1 = ks[kA+1], a2 = ks[kA+2], a3 = ks[kA+3];
                        unsigned long long v0 = __ldg(xs2 + (size_t)a0 * 32 + lane);
                        unsigned long long v1 = __ldg(xs2 + (size_t)a1 * 32 + lane);
                        unsigned long long v2 = __ldg(xs2 + (size_t)a2 * 32 + lane);
                        unsigned long long v3 = __ldg(xs2 + (size_t)a3 * 32 + lane);
                        fadd2(v0, v1); fadd2(v2, v3); fadd2(v0, v2); fadd2(aA, v0);
                        kA += 4;
                    }
                    while (kB + 3 < eB) {
                        int b0 = ks[kB], b1 = ks[kB+1], b2 = ks[kB+2], b3 = ks[kB+3];
                        unsigned long long v0 = __ldg(xs2 + (size_t)b0 * 32 + lane);
                        unsigned long long v1 = __ldg(xs2 + (size_t)b1 * 32 + lane);
                        unsigned long long v2 = __ldg(xs2 + (size_t)b2 * 32 + lane);
                        unsigned long long v3 = __ldg(xs2 + (size_t)b3 * 32 + lane);
                        fadd2(v0, v1); fadd2(v2, v3); fadd2(v0, v2); fadd2(aB, v0);
                        kB += 4;
                    }
                    // batched predicated tails: all 6 LDGs in one wave
                    {
                        int rA = eA - kA;           // 0..3
                        int rB = eB - kB;           // 0..3
                        unsigned long long t0 = 0ull, t1 = 0ull, t2 = 0ull;
                        unsigned long long u0 = 0ull, u1 = 0ull, u2 = 0ull;
                        if (rA > 0) t0 = __ldg(xs2 + (size_t)ks[kA]     * 32 + lane);
                        if (rA > 1) t1 = __ldg(xs2 + (size_t)ks[kA + 1] * 32 + lane);
                        if (rA > 2) t2 = __ldg(xs2 + (size_t)ks[kA + 2] * 32 + lane);
                        if (rB > 0) u0 = __ldg(xs2 + (size_t)ks[kB]     * 32 + lane);
                        if (rB > 1) u1 = __ldg(xs2 + (size_t)ks[kB + 1] * 32 + lane);
                        if (rB > 2) u2 = __ldg(xs2 + (size_t)ks[kB + 2] * 32 + lane);
                        fadd2(t0, t1); fadd2(t0, t2); fadd2(aA, t0);
                        fadd2(u0, u1); fadd2(u0, u2); fadd2(aB, u0);
                    }
                    int degA = eA - sA, degB = eB - sB;
                    fmul2(aA, pack2(1.0f / (float)(degA > 1 ? degA : 1)));
                    fmul2(aB, pack2(1.0f / (float)(degB > 1 ? degB : 1)));
                    ((unsigned long long*)(Xs + lrA * XS_STRIDE))[lane] = aA;
                    ((unsigned long long*)(Xs + lrB * XS_STRIDE))[lane] = aB;
                }
            } else {
                // rare fallback: direct global CSR reads, per-row sequential
#pragma unroll 1
                for (int i = 0; i < 8; i++) {
                    int lr = w * 8 + i;
                    unsigned long long a = 0ull;
                    if (lr < nrows) {
                        int s = off_s[lr];
                        int e = off_s[lr + 1];
                        for (int k = s; k < e; k++) {
                            int i0 = __ldg(csr + k);
                            unsigned long long v0 = __ldg(xs2 + (size_t)i0 * 32 + lane);
                            fadd2(a, v0);
                        }
                        int deg = e - s;
                        fmul2(a, pack2(1.0f / (float)(deg > 1 ? deg : 1)));
                    }
                    ((unsigned long long*)(Xs + lr * XS_STRIDE))[lane] = a;
                }
            }
        }
        __syncthreads();
        // --- packed FFMA: 4 rows x 4 cols per thread ---
#pragma unroll
        for (int k4 = 0; k4 < 16; k4++) {
            float4 xr[4];
#pragma unroll
            for (int i = 0; i < 4; i++)
                xr[i] = *(const float4*)(Xs + (ty * 4 + i) * XS_STRIDE + k4 * 4);
#pragma unroll
            for (int j = 0; j < 4; j++) {
                ulonglong2 wv = ((ulonglong2*)Ws)[(k4 * 4 + j) * 16 + tx];
#pragma unroll
                for (int i = 0; i < 4; i++) {
                    unsigned long long aa = pack2((&xr[i].x)[j]);
                    ffma2(acc01[i], aa, wv.x);
                    ffma2(acc23[i], aa, wv.y);
                }
            }
        }
        __syncthreads();
    }

    float4 bb = *(const float4*)(p.bsum + t * 64 + tx * 4);
    float* out = p.out[t];
#pragma unroll
    for (int i = 0; i < 4; i++) {
        int gr = row0 + ty * 4 + i;
        if (gr < n) {
            float2 lo = *(float2*)&acc01[i];
            float2 hi = *(float2*)&acc23[i];
            float4 o;
            o.x = fmaxf(lo.x + bb.x, 0.f);
            o.y = fmaxf(lo.y + bb.y, 0.f);
            o.z = fmaxf(hi.x + bb.z, 0.f);
            o.w = fmaxf(hi.y + bb.w, 0.f);
            *(float4*)(out + (size_t)gr * H + tx * 4) = o;
        }
    }
}

// ---------------------------------------------------------------------------
// Head: out[row] = softplus(cell[row] @ projW + projb) @ outW + outb
// ---------------------------------------------------------------------------
__global__ void head_k(const float* __restrict__ X, const float* __restrict__ W,
                       const float* __restrict__ b, const float* __restrict__ ow,
                       const float* __restrict__ ob, float* __restrict__ out, int n) {
    __shared__ float Ws[H * H];
    for (int i = threadIdx.x; i < H * H; i += blockDim.x) Ws[i] = W[i];
    __syncthreads();

    int warp = threadIdx.x >> 5;
    int lane = threadIdx.x & 31;
    int row  = blockIdx.x * (blockDim.x >> 5) + warp;
    if (row >= n) return;

    const float* x = X + (size_t)row * H;
    float in_lo = x[lane];
    float in_hi = x[lane + 32];
    float a0 = b[lane];
    float a1 = b[lane + 32];

#pragma unroll
    for (int k = 0; k < 32; k++) {
        float a = __shfl_sync(0xffffffffu, in_lo, k);
        a0 += a * Ws[k * H + lane];
        a1 += a * Ws[k * H + lane + 32];
    }
#pragma unroll
    for (int k = 0; k < 32; k++) {
        float a = __shfl_sync(0xffffffffu, in_hi, k);
        a0 += a * Ws[(k + 32) * H + lane];
        a1 += a * Ws[(k + 32) * H + lane + 32];
    }
    a0 = fmaxf(a0, 0.0f) + log1pf(expf(-fabsf(a0)));
    a1 = fmaxf(a1, 0.0f) + log1pf(expf(-fabsf(a1)));
    float s = a0 * ow[lane] + a1 * ow[lane + 32];
#pragma unroll
    for (int o = 16; o > 0; o >>= 1) s += __shfl_down_sync(0xffffffffu, s, o);
    if (lane == 0) out[row] = s + ob[0];
}

// ---------------------------------------------------------------------------
// Host orchestration
// ---------------------------------------------------------------------------
extern "C" void kernel_launch(void* const* d_in, const int* in_sizes, int n_in,
                              void* d_out, int out_size) {
    const float* x_in[4] = {(const float*)d_in[0], (const float*)d_in[1],
                            (const float*)d_in[2], (const float*)d_in[3]};
    const float* Wl    = (const float*)d_in[4];
    const float* bl    = (const float*)d_in[5];
    const float* Wr    = (const float*)d_in[6];
    const float* projW = (const float*)d_in[7];
    const float* projb = (const float*)d_in[8];
    const float* outW  = (const float*)d_in[9];
    const float* outb  = (const float*)d_in[10];

    EdgeP ep;
    for (int r = 0; r < 9; r++) {
        ep.ei[r] = (const int*)d_in[11 + r];
        ep.E[r]  = in_sizes[11 + r] / 2;
    }

    const int ROFF[4] = {0, 100000, 300000, 350000};

    float *buf0, *buf1, *Wst, *bsum;
    int *cnt, *off, *cursor, *bsums, *csr;
    cudaGetSymbolAddress((void**)&buf0,   g_xbuf0);
    cudaGetSymbolAddress((void**)&buf1,   g_xbuf1);
    cudaGetSymbolAddress((void**)&cnt,    g_cnt);
    cudaGetSymbolAddress((void**)&off,    g_off);
    cudaGetSymbolAddress((void**)&cursor, g_cursor);
    cudaGetSymbolAddress((void**)&bsums,  g_bsums);
    cudaGetSymbolAddress((void**)&csr,    g_csr);
    cudaGetSymbolAddress((void**)&Wst,    g_Wst);
    cudaGetSymbolAddress((void**)&bsum,   g_bsum);

    const int TB = 256;

    // 1. setup: weight stacking + bias sums + cnt zeroing (one launch)
    setup_k<<<(WB_TOTAL + NSCAN + TB - 1) / TB, TB>>>(Wr, Wl, bl, Wst, bsum, cnt);

    // 2. CSR build: count, block-sums, scan(+cursor), fill  (4 launches)
    count_all_k<<<2048, TB>>>(ep, cnt);
    scan1_k<<<SCAN_NBLK, 256>>>(cnt, bsums);
    scan3_k<<<SCAN_NBLK, 256>>>(cnt, bsums, off, cursor);
    fill_k<<<2048, TB>>>(ep, cursor, csr);

    // 3. layers
    for (int l = 0; l < NL; l++) {
        GemmP gp;
        float* xnext = (l % 2 == 0) ? buf0 : buf1;
        const float* prev = (l % 2 == 0) ? buf1 : buf0;
        for (int t = 0; t < 4; t++) {
            gp.x[t]   = (l == 0) ? x_in[t] : (prev + (size_t)ROFF[t] * H);
            gp.out[t] = xnext + (size_t)ROFF[t] * H;
        }
        gp.Wst  = Wst + (size_t)l * WST_LAYER;
        gp.bsum = bsum + (size_t)l * 4 * H;
        gp.off  = off;
        gp.csr  = csr;
        gemm_gather_k<<<GRID_GEMM, TB>>>(gp);
    }

    // 4. head
    {
        const float* xcell = buf0 + (size_t)ROFF[3] * H;
        int rows_per_block = TB / 32;
        int g = (N_CELL + rows_per_block - 1) / rows_per_block;
        head_k<<<g, TB>>>(xcell, projW, projb, outW, outb, (float*)d_out, N_CELL);
    }
}

// round 17
// speedup vs baseline: 1.8942x; 1.0440x over previous
#include <cuda_runtime.h>
#include <cstdint>
#include <cstddef>

// ---------------------------------------------------------------------------
// Problem constants
// ---------------------------------------------------------------------------
#define H 64
#define NL 3
#define N_ATOM  100000
#define N_BOND  200000
#define N_MOTIF 50000
#define N_CELL  5000
#define NTOT    355000

#define NCNT    665000
#define NSCAN   665001
#define MAXE    3000000
#define WST_LAYER 53248           // (128+192+256+256)*64
#define WB_TOTAL  (NL * WST_LAYER + NL * 4 * H)

#define SCAN_TILE 1024
#define SCAN_NBLK ((NSCAN + SCAN_TILE - 1) / SCAN_TILE)   // 650

#define CSR_PER_WARP 384          // warp-private staged CSR span (ints)
// Block smem: 16384 (Xs) + 16384 (Ws) + 8*384*4 (csr_s) = 45056 B -> occ 4.

// ---------------------------------------------------------------------------
// Static scratch
// ---------------------------------------------------------------------------
__device__ __align__(16) float g_xbuf0[NTOT * H];
__device__ __align__(16) float g_xbuf1[NTOT * H];
__device__ __align__(16) int   g_cnt[NSCAN];
__device__ __align__(16) int   g_off[NSCAN];
__device__ __align__(16) int   g_cursor[NCNT];
__device__ __align__(16) int   g_bsums[SCAN_NBLK];
__device__ __align__(16) int   g_csr[MAXE];
__device__ __align__(16) float g_Wst[NL * WST_LAYER];
__device__ __align__(16) float g_bsum[NL * 4 * H];

// Constant tables
__device__ __constant__ int c_CO[9]   = {0, 100000, 300000, 350000, 550000,
                                         600000, 650000, 655000, 660000};
__device__ __constant__ int c_SRCT[9] = {0, 0, 0, 1, 1, 2, 0, 1, 2};
__device__ __constant__ int c_RID[4][3] = {{0,0,0},{1,3,0},{2,4,5},{6,7,8}};
__device__ __constant__ int c_NT[4]   = {N_ATOM, N_BOND, N_MOTIF, N_CELL};
__device__ __constant__ int c_NCH[4]  = {2, 3, 4, 4};
__device__ __constant__ int c_WOFF[4] = {0, 8192, 20480, 36864};

// ---------------------------------------------------------------------------
// Packed fp32x2 helpers
// ---------------------------------------------------------------------------
__device__ __forceinline__ void ffma2(unsigned long long& acc,
                                      unsigned long long a,
                                      unsigned long long b) {
    asm("fma.rn.f32x2 %0, %1, %2, %0;" : "+l"(acc) : "l"(a), "l"(b));
}
__device__ __forceinline__ void fadd2(unsigned long long& acc,
                                      unsigned long long v) {
    asm("add.rn.f32x2 %0, %1, %0;" : "+l"(acc) : "l"(v));
}
__device__ __forceinline__ void fmul2(unsigned long long& acc,
                                      unsigned long long v) {
    asm("mul.rn.f32x2 %0, %1, %0;" : "+l"(acc) : "l"(v));
}
__device__ __forceinline__ unsigned long long pack2(float a) {
    unsigned long long d;
    asm("mov.b64 %0, {%1, %1};" : "=l"(d) : "f"(a));
    return d;
}

// ---------------------------------------------------------------------------
// Setup: weight stacking + bias sums + cnt zeroing in ONE kernel
// ---------------------------------------------------------------------------
__global__ void setup_k(const float* __restrict__ Wr, const float* __restrict__ Wl,
                        const float* __restrict__ bl,
                        float* __restrict__ Wst, float* __restrict__ bsum,
                        int* __restrict__ cnt) {
    int i = blockIdx.x * blockDim.x + threadIdx.x;
    const int woff[5]     = {0, 8192, 20480, 36864, 53248};
    const int rcnt[4]     = {1, 2, 3, 3};
    const int rlist[4][3] = {{0,0,0},{1,3,0},{2,4,5},{6,7,8}};
    if (i < NL * WST_LAYER) {
        int l = i / WST_LAYER;
        int rem = i - l * WST_LAYER;
        int t = 0;
        while (rem >= woff[t + 1]) t++;
        int local = rem - woff[t];
        int krow = local >> 6;
        int col  = local & 63;
        float v;
        if (krow < 64) {
            v = 0.0f;
            for (int j = 0; j < rcnt[t]; j++)
                v += Wr[((size_t)(l * 9 + rlist[t][j]) * 64 + krow) * 64 + col];
        } else {
            int s = (krow >> 6) - 1;
            int r = rlist[t][s];
            int kk = krow & 63;
            v = Wl[((size_t)(l * 9 + r) * 64 + kk) * 64 + col];
        }
        Wst[i] = v;
    } else if (i < WB_TOTAL) {
        int j2 = i - NL * WST_LAYER;
        int l = j2 / (4 * H);
        int rem = j2 - l * 4 * H;
        int t = rem >> 6;
        int col = rem & 63;
        float v = 0.0f;
        for (int j = 0; j < rcnt[t]; j++)
            v += bl[(size_t)(l * 9 + rlist[t][j]) * H + col];
        bsum[j2] = v;
    } else if (i < WB_TOTAL + NSCAN) {
        cnt[i - WB_TOTAL] = 0;
    }
}

// ---------------------------------------------------------------------------
// CSR build.  Edge indices are int32, layout [2,E]: src then dst.
// ---------------------------------------------------------------------------
struct EdgeP {
    const int* ei[9];
    int E[9];
};

__global__ void count_all_k(EdgeP p, int* __restrict__ cnt) {
    int gsz = gridDim.x * blockDim.x;
    int t0  = blockIdx.x * blockDim.x + threadIdx.x;
#pragma unroll
    for (int r = 0; r < 9; r++) {
        const int* d = p.ei[r] + p.E[r];
        int* c = cnt + c_CO[r];
        int E = p.E[r];
        for (int e = t0; e < E; e += gsz) atomicAdd(c + __ldg(d + e), 1);
    }
}

__global__ void scan1_k(const int* __restrict__ in, int* __restrict__ bsums) {
    __shared__ int s[256];
    int b = blockIdx.x, tid = threadIdx.x;
    int base = b * SCAN_TILE + tid * 4;
    int t = 0;
#pragma unroll
    for (int j = 0; j < 4; j++) {
        int i = base + j;
        if (i < NSCAN) t += in[i];
    }
    s[tid] = t;
    __syncthreads();
    for (int d = 128; d > 0; d >>= 1) {
        if (tid < d) s[tid] += s[tid + d];
        __syncthreads();
    }
    if (tid == 0) bsums[b] = s[0];
}

// scan3 (absorbs scan2): each block computes its own prefix over bsums,
// then local exclusive scan + base -> off AND cursor.
__global__ void scan3_k(const int* __restrict__ in, const int* __restrict__ bsums,
                        int* __restrict__ off, int* __restrict__ cur) {
    __shared__ int s[256];
    __shared__ int blockbase;
    int b = blockIdx.x, tid = threadIdx.x;

    int bv = 0;
    for (int j = tid; j < b; j += 256) bv += __ldg(bsums + j);
    s[tid] = bv;
    __syncthreads();
    for (int d = 128; d > 0; d >>= 1) {
        if (tid < d) s[tid] += s[tid + d];
        __syncthreads();
    }
    if (tid == 0) blockbase = s[0];
    __syncthreads();

    int base = b * SCAN_TILE + tid * 4;
    int v[4];
    int t = 0;
#pragma unroll
    for (int j = 0; j < 4; j++) {
        int i = base + j;
        v[j] = (i < NSCAN) ? in[i] : 0;
        t += v[j];
    }
    s[tid] = t;
    __syncthreads();
    for (int d = 1; d < 256; d <<= 1) {
        int x = (tid >= d) ? s[tid - d] : 0;
        __syncthreads();
        s[tid] += x;
        __syncthreads();
    }
    int run = blockbase + s[tid] - t;
#pragma unroll
    for (int j = 0; j < 4; j++) {
        int i = base + j;
        if (i < NSCAN) {
            off[i] = run;
            if (i < NCNT) cur[i] = run;
        }
        run += v[j];
    }
}

__global__ void fill_k(EdgeP p, int* __restrict__ cursor, int* __restrict__ csr) {
    int gsz = gridDim.x * blockDim.x;
    int t0  = blockIdx.x * blockDim.x + threadIdx.x;
#pragma unroll
    for (int r = 0; r < 9; r++) {
        const int* s = p.ei[r];
        const int* d = p.ei[r] + p.E[r];
        int* c = cursor + c_CO[r];
        int E = p.E[r];
        for (int e = t0; e < E; e += gsz) {
            int pos = atomicAdd(c + __ldg(d + e), 1);
            csr[pos] = __ldg(s + e);
        }
    }
}

// ---------------------------------------------------------------------------
// Fused layer kernel: 64-row tiles, 4x4 f32x2 micro-tile (R13 FFMA core),
// WARP-PRIVATE CSR staging (no block barriers in the gather phase),
// dual-row 4-wide gather chains + batched predicated tails.
// Grid block -> (type, tile): atom 1563 | bond 3125 | motif 782 | cell 79.
// ---------------------------------------------------------------------------
#define GRID_GEMM 5549

struct GemmP {
    const float* x[4];
    float* out[4];
    const float* Wst;
    const float* bsum;
    const int* off;
    const int* csr;
};

__global__ void __launch_bounds__(256, 4)
gemm_gather_k(GemmP p) {
    __shared__ __align__(16) float Xs[64 * 64];          // 16KB
    __shared__ __align__(16) float Ws[64 * 64];          // 16KB
    __shared__ __align__(16) int   csr_s[8 * CSR_PER_WARP]; // 12KB

    int b = blockIdx.x;
    int t, row0;
    if (b < 1563)      { t = 0; row0 = b * 64; }
    else if (b < 4688) { t = 1; row0 = (b - 1563) * 64; }
    else if (b < 5470) { t = 2; row0 = (b - 4688) * 64; }
    else               { t = 3; row0 = (b - 5470) * 64; }

    const int n       = c_NT[t];
    const int nchunks = c_NCH[t];
    const float* W0   = p.Wst + c_WOFF[t];
    const float* X    = p.x[t];

    const int tid  = threadIdx.x;
    const int tx   = tid & 15;
    const int ty   = tid >> 4;
    const int w    = tid >> 5;
    const int lane = tid & 31;

    unsigned long long acc01[4], acc23[4];
#pragma unroll
    for (int i = 0; i < 4; i++) { acc01[i] = 0ull; acc23[i] = 0ull; }

    for (int c = 0; c < nchunks; c++) {
        // --- load W chunk (4096 floats) ---
#pragma unroll
        for (int i = 0; i < 4; i++) {
            int idx = tid + i * 256;
            ((float4*)Ws)[idx] = ((const float4*)(W0 + c * 4096))[idx];
        }
        // --- fill X chunk ---
        if (c == 0) {
#pragma unroll
            for (int i = 0; i < 4; i++) {
                int idx = tid + i * 256;
                int lr = idx >> 4;
                int c4 = idx & 15;
                int gr = row0 + lr;
                float4 v = make_float4(0.f, 0.f, 0.f, 0.f);
                if (gr < n) v = *(const float4*)(X + (size_t)gr * H + c4 * 4);
                ((float4*)Xs)[idx] = v;
            }
        } else {
            int rel = c_RID[t][c - 1];
            const unsigned long long* __restrict__ xs2 =
                (const unsigned long long*)p.x[c_SRCT[rel]];   // row = 32 u64
            const int* __restrict__ offr = p.off + c_CO[rel];
            const int* __restrict__ csr  = p.csr;

            // warp-private offsets: lanes 0..8 load off[row0 + w*8 + lane]
            int lr0 = w * 8;
            int o = 0;
            {
                int gr = row0 + lr0 + lane;
                if (gr > n) gr = n;
                if (lane <= 8) o = __ldg(offr + gr);
            }
            int baseW = __shfl_sync(0xffffffffu, o, 0);
            int endW  = __shfl_sync(0xffffffffu, o, 8);
            int spanW = endW - baseW;
            int* csr_w = csr_s + w * CSR_PER_WARP;
            bool staged = (spanW <= CSR_PER_WARP);
            if (staged) {
                for (int i = lane; i < spanW; i += 32)
                    csr_w[i] = __ldg(csr + baseW + i);
            }
            __syncwarp();

            if (staged) {
                const int* ks = csr_w - baseW;
#pragma unroll 1
                for (int i = 0; i < 4; i++) {
                    int lrA = lr0 + i;
                    int lrB = lrA + 4;
                    int sA = __shfl_sync(0xffffffffu, o, i);
                    int eA = __shfl_sync(0xffffffffu, o, i + 1);
                    int sB = __shfl_sync(0xffffffffu, o, i + 4);
                    int eB = __shfl_sync(0xffffffffu, o, i + 5);
                    unsigned long long aA = 0ull, aB = 0ull;
                    int kA = sA, kB = sB;
                    // dual independent 4-wide chains (MLP 8)
                    while (kA + 3 < eA && kB + 3 < eB) {
                        int a0 = ks[kA], a1 = ks[kA+1], a2 = ks[kA+2], a3 = ks[kA+3];
                        int b0 = ks[kB], b1 = ks[kB+1], b2 = ks[kB+2], b3 = ks[kB+3];
                        unsigned long long vA0 = __ldg(xs2 + (size_t)a0 * 32 + lane);
                        unsigned long long vA1 = __ldg(xs2 + (size_t)a1 * 32 + lane);
                        unsigned long long vA2 = __ldg(xs2 + (size_t)a2 * 32 + lane);
                        unsigned long long vA3 = __ldg(xs2 + (size_t)a3 * 32 + lane);
                        unsigned long long vB0 = __ldg(xs2 + (size_t)b0 * 32 + lane);
                        unsigned long long vB1 = __ldg(xs2 + (size_t)b1 * 32 + lane);
                        unsigned long long vB2 = __ldg(xs2 + (size_t)b2 * 32 + lane);
                        unsigned long long vB3 = __ldg(xs2 + (size_t)b3 * 32 + lane);
                        fadd2(vA0, vA1); fadd2(vA2, vA3); fadd2(vA0, vA2); fadd2(aA, vA0);
                        fadd2(vB0, vB1); fadd2(vB2, vB3); fadd2(vB0, vB2); fadd2(aB, vB0);
                        kA += 4; kB += 4;
                    }
                    while (kA + 3 < eA) {
                        int a0 = ks[kA], a1 = ks[kA+1], a2 = ks[kA+2], a3 = ks[kA+3];
                        unsigned long long v0 = __ldg(xs2 + (size_t)a0 * 32 + lane);
                        unsigned long long v1 = __ldg(xs2 + (size_t)a1 * 32 + lane);
                        unsigned long long v2 = __ldg(xs2 + (size_t)a2 * 32 + lane);
                        unsigned long long v3 = __ldg(xs2 + (size_t)a3 * 32 + lane);
                        fadd2(v0, v1); fadd2(v2, v3); fadd2(v0, v2); fadd2(aA, v0);
                        kA += 4;
                    }
                    while (kB + 3 < eB) {
                        int b0 = ks[kB], b1 = ks[kB+1], b2 = ks[kB+2], b3 = ks[kB+3];
                        unsigned long long v0 = __ldg(xs2 + (size_t)b0 * 32 + lane);
                        unsigned long long v1 = __ldg(xs2 + (size_t)b1 * 32 + lane);
                        unsigned long long v2 = __ldg(xs2 + (size_t)b2 * 32 + lane);
                        unsigned long long v3 = __ldg(xs2 + (size_t)b3 * 32 + lane);
                        fadd2(v0, v1); fadd2(v2, v3); fadd2(v0, v2); fadd2(aB, v0);
                        kB += 4;
                    }
                    // batched predicated tails: all 6 LDGs in one wave
                    {
                        int rA = eA - kA;           // 0..3
                        int rB = eB - kB;           // 0..3
                        unsigned long long t0 = 0ull, t1 = 0ull, t2 = 0ull;
                        unsigned long long u0 = 0ull, u1 = 0ull, u2 = 0ull;
                        if (rA > 0) t0 = __ldg(xs2 + (size_t)ks[kA]     * 32 + lane);
                        if (rA > 1) t1 = __ldg(xs2 + (size_t)ks[kA + 1] * 32 + lane);
                        if (rA > 2) t2 = __ldg(xs2 + (size_t)ks[kA + 2] * 32 + lane);
                        if (rB > 0) u0 = __ldg(xs2 + (size_t)ks[kB]     * 32 + lane);
                        if (rB > 1) u1 = __ldg(xs2 + (size_t)ks[kB + 1] * 32 + lane);
                        if (rB > 2) u2 = __ldg(xs2 + (size_t)ks[kB + 2] * 32 + lane);
                        fadd2(t0, t1); fadd2(t0, t2); fadd2(aA, t0);
                        fadd2(u0, u1); fadd2(u0, u2); fadd2(aB, u0);
                    }
                    int degA = eA - sA, degB = eB - sB;
                    fmul2(aA, pack2(1.0f / (float)(degA > 1 ? degA : 1)));
                    fmul2(aB, pack2(1.0f / (float)(degB > 1 ? degB : 1)));
                    ((unsigned long long*)(Xs + lrA * 64))[lane] = aA;
                    ((unsigned long long*)(Xs + lrB * 64))[lane] = aB;
                }
            } else {
                // rare fallback: direct global CSR reads, per-row sequential
#pragma unroll 1
                for (int i = 0; i < 8; i++) {
                    int lr = lr0 + i;
                    int s = __shfl_sync(0xffffffffu, o, i);
                    int e = __shfl_sync(0xffffffffu, o, i + 1);
                    unsigned long long a = 0ull;
                    for (int k = s; k < e; k++) {
                        int i0 = __ldg(csr + k);
                        unsigned long long v0 = __ldg(xs2 + (size_t)i0 * 32 + lane);
                        fadd2(a, v0);
                    }
                    int deg = e - s;
                    fmul2(a, pack2(1.0f / (float)(deg > 1 ? deg : 1)));
                    ((unsigned long long*)(Xs + lr * 64))[lane] = a;
                }
            }
        }
        __syncthreads();
        // --- packed FFMA: 4 rows x 4 cols per thread (R13 core, untouched) ---
#pragma unroll
        for (int k4 = 0; k4 < 16; k4++) {
            float4 xr[4];
#pragma unroll
            for (int i = 0; i < 4; i++)
                xr[i] = ((float4*)Xs)[(ty * 4 + i) * 16 + k4];
#pragma unroll
            for (int j = 0; j < 4; j++) {
                ulonglong2 wv = ((ulonglong2*)Ws)[(k4 * 4 + j) * 16 + tx];
#pragma unroll
                for (int i = 0; i < 4; i++) {
                    unsigned long long aa = pack2((&xr[i].x)[j]);
                    ffma2(acc01[i], aa, wv.x);
                    ffma2(acc23[i], aa, wv.y);
                }
            }
        }
        __syncthreads();
    }

    float4 bb = *(const float4*)(p.bsum + t * 64 + tx * 4);
    float* out = p.out[t];
#pragma unroll
    for (int i = 0; i < 4; i++) {
        int gr = row0 + ty * 4 + i;
        if (gr < n) {
            float2 lo = *(float2*)&acc01[i];
            float2 hi = *(float2*)&acc23[i];
            float4 o;
            o.x = fmaxf(lo.x + bb.x, 0.f);
            o.y = fmaxf(lo.y + bb.y, 0.f);
            o.z = fmaxf(hi.x + bb.z, 0.f);
            o.w = fmaxf(hi.y + bb.w, 0.f);
            *(float4*)(out + (size_t)gr * H + tx * 4) = o;
        }
    }
}

// ---------------------------------------------------------------------------
// Head: out[row] = softplus(cell[row] @ projW + projb) @ outW + outb
// ---------------------------------------------------------------------------
__global__ void head_k(const float* __restrict__ X, const float* __restrict__ W,
                       const float* __restrict__ b, const float* __restrict__ ow,
                       const float* __restrict__ ob, float* __restrict__ out, int n) {
    __shared__ float Ws[H * H];
    for (int i = threadIdx.x; i < H * H; i += blockDim.x) Ws[i] = W[i];
    __syncthreads();

    int warp = threadIdx.x >> 5;
    int lane = threadIdx.x & 31;
    int row  = blockIdx.x * (blockDim.x >> 5) + warp;
    if (row >= n) return;

    const float* x = X + (size_t)row * H;
    float in_lo = x[lane];
    float in_hi = x[lane + 32];
    float a0 = b[lane];
    float a1 = b[lane + 32];

#pragma unroll
    for (int k = 0; k < 32; k++) {
        float a = __shfl_sync(0xffffffffu, in_lo, k);
        a0 += a * Ws[k * H + lane];
        a1 += a * Ws[k * H + lane + 32];
    }
#pragma unroll
    for (int k = 0; k < 32; k++) {
        float a = __shfl_sync(0xffffffffu, in_hi, k);
        a0 += a * Ws[(k + 32) * H + lane];
        a1 += a * Ws[(k + 32) * H + lane + 32];
    }
    a0 = fmaxf(a0, 0.0f) + log1pf(expf(-fabsf(a0)));
    a1 = fmaxf(a1, 0.0f) + log1pf(expf(-fabsf(a1)));
    float s = a0 * ow[lane] + a1 * ow[lane + 32];
#pragma unroll
    for (int o = 16; o > 0; o >>= 1) s += __shfl_down_sync(0xffffffffu, s, o);
    if (lane == 0) out[row] = s + ob[0];
}

// ---------------------------------------------------------------------------
// Host orchestration
// ---------------------------------------------------------------------------
extern "C" void kernel_launch(void* const* d_in, const int* in_sizes, int n_in,
                              void* d_out, int out_size) {
    const float* x_in[4] = {(const float*)d_in[0], (const float*)d_in[1],
                            (const float*)d_in[2], (const float*)d_in[3]};
    const float* Wl    = (const float*)d_in[4];
    const float* bl    = (const float*)d_in[5];
    const float* Wr    = (const float*)d_in[6];
    const float* projW = (const float*)d_in[7];
    const float* projb = (const float*)d_in[8];
    const float* outW  = (const float*)d_in[9];
    const float* outb  = (const float*)d_in[10];

    EdgeP ep;
    for (int r = 0; r < 9; r++) {
        ep.ei[r] = (const int*)d_in[11 + r];
        ep.E[r]  = in_sizes[11 + r] / 2;
    }

    const int ROFF[4] = {0, 100000, 300000, 350000};

    float *buf0, *buf1, *Wst, *bsum;
    int *cnt, *off, *cursor, *bsums, *csr;
    cudaGetSymbolAddress((void**)&buf0,   g_xbuf0);
    cudaGetSymbolAddress((void**)&buf1,   g_xbuf1);
    cudaGetSymbolAddress((void**)&cnt,    g_cnt);
    cudaGetSymbolAddress((void**)&off,    g_off);
    cudaGetSymbolAddress((void**)&cursor, g_cursor);
    cudaGetSymbolAddress((void**)&bsums,  g_bsums);
    cudaGetSymbolAddress((void**)&csr,    g_csr);
    cudaGetSymbolAddress((void**)&Wst,    g_Wst);
    cudaGetSymbolAddress((void**)&bsum,   g_bsum);

    const int TB = 256;

    // 1. setup: weight stacking + bias sums + cnt zeroing (one launch)
    setup_k<<<(WB_TOTAL + NSCAN + TB - 1) / TB, TB>>>(Wr, Wl, bl, Wst, bsum, cnt);

    // 2. CSR build: count, block-sums, scan(+cursor), fill  (4 launches)
    count_all_k<<<2048, TB>>>(ep, cnt);
    scan1_k<<<SCAN_NBLK, 256>>>(cnt, bsums);
    scan3_k<<<SCAN_NBLK, 256>>>(cnt, bsums, off, cursor);
    fill_k<<<2048, TB>>>(ep, cursor, csr);

    // 3. layers
    for (int l = 0; l < NL; l++) {
        GemmP gp;
        float* xnext = (l % 2 == 0) ? buf0 : buf1;
        const float* prev = (l % 2 == 0) ? buf1 : buf0;
        for (int t = 0; t < 4; t++) {
            gp.x[t]   = (l == 0) ? x_in[t] : (prev + (size_t)ROFF[t] * H);
            gp.out[t] = xnext + (size_t)ROFF[t] * H;
        }
        gp.Wst  = Wst + (size_t)l * WST_LAYER;
        gp.bsum = bsum + (size_t)l * 4 * H;
        gp.off  = off;
        gp.csr  = csr;
        gemm_gather_k<<<GRID_GEMM, TB>>>(gp);
    }

    // 4. head
    {
        const float* xcell = buf0 + (size_t)ROFF[3] * H;
        int rows_per_block = TB / 32;
        int g = (N_CELL + rows_per_block - 1) / rows_per_block;
        head_k<<<g, TB>>>(xcell, projW, projb, outW, outb, (float*)d_out, N_CELL);
    }
}